// round 5
// baseline (speedup 1.0000x reference)
#include <cuda_runtime.h>

// Problem constants
#define LAYERS 12
#define BATCH  16
#define HEADS  12
#define N      197
#define KSEL   98            // int(197 * 0.5)

// ---------------------------------------------------------------------------
// Kernel 0: paint output with the "unselected" one-hot (1, 0).
// out shape: [BATCH, N, 2] float32.
// ---------------------------------------------------------------------------
__global__ void init_out_kernel(float* __restrict__ out) {
    int t = blockIdx.x * blockDim.x + threadIdx.x;   // over BATCH*N
    if (t < BATCH * N) {
        out[2 * t + 0] = 1.0f;
        out[2 * t + 1] = 0.0f;
    }
}

// ---------------------------------------------------------------------------
// Kernel 1: one CTA per (modality, b, h).  224 threads (7 warps; tid<197 work).
//   v = row 0 of A[11];  for l = 10..0:  v <- v^T * A[l]
//   scores s[j] = v[j+1], j in [0, 196); stable top-98 (lower index wins
//   ties, == lax.top_k order); selected tokens write (0,1) into out.
//   Cross-CTA write races are benign: all writers store the same value.
//
// Memory: inner loop over i reads A[l][i][j], j = lane -> contiguous 788B
// row segments, fully coalesced. __ldcs: each matrix is streamed once.
// 8-way unroll -> 8 independent LDGs in flight per thread.
// v is double-buffered in shared -> one __syncthreads per layer.
// ---------------------------------------------------------------------------
__global__ __launch_bounds__(224, 8)
void chain_select_kernel(const float* __restrict__ rgb,
                         const float* __restrict__ tir,
                         float* __restrict__ out) {
    const int bid = blockIdx.x;                 // [0, 2*BATCH*HEADS)
    const int mod = bid / (BATCH * HEADS);
    const int bh  = bid % (BATCH * HEADS);
    const int b   = bh / HEADS;

    const float* base = (mod == 0) ? rgb : tir;
    const size_t mat  = (size_t)N * N;

    __shared__ float vbuf[2][N];

    const int tid = threadIdx.x;

    // Init: vbuf[0] = A[11][b][h][0][:]  (only row 0 of layer 11 is needed)
    {
        const float* a11 = base + ((size_t)11 * BATCH * HEADS + (size_t)bh) * mat;
        if (tid < N) vbuf[0][tid] = __ldcs(&a11[tid]);
    }
    __syncthreads();

    // Chain: v <- v^T * A[l], l = 10 down to 0.  Ping-pong buffers: read
    // cur, write 1-cur, single barrier per layer.
    int cur = 0;
    for (int l = 10; l >= 0; --l) {
        const float* __restrict__ A =
            base + ((size_t)l * BATCH * HEADS + (size_t)bh) * mat;
        const float* __restrict__ v = vbuf[cur];

        float acc = 0.0f;
        if (tid < N) {
            const float* col = A + tid;      // stride-N walk down column tid
            int i = 0;
            #pragma unroll 1
            for (; i + 8 <= N; i += 8) {
                float a0 = __ldcs(&col[(size_t)(i + 0) * N]);
                float a1 = __ldcs(&col[(size_t)(i + 1) * N]);
                float a2 = __ldcs(&col[(size_t)(i + 2) * N]);
                float a3 = __ldcs(&col[(size_t)(i + 3) * N]);
                float a4 = __ldcs(&col[(size_t)(i + 4) * N]);
                float a5 = __ldcs(&col[(size_t)(i + 5) * N]);
                float a6 = __ldcs(&col[(size_t)(i + 6) * N]);
                float a7 = __ldcs(&col[(size_t)(i + 7) * N]);
                acc += v[i + 0] * a0; acc += v[i + 1] * a1;
                acc += v[i + 2] * a2; acc += v[i + 3] * a3;
                acc += v[i + 4] * a4; acc += v[i + 5] * a5;
                acc += v[i + 6] * a6; acc += v[i + 7] * a7;
            }
            for (; i < N; ++i) {
                acc += v[i] * __ldcs(&col[(size_t)i * N]);
            }
            vbuf[1 - cur][tid] = acc;        // write next v (other buffer)
        }
        __syncthreads();                     // next-v complete; cur freed
        cur = 1 - cur;
    }

    // Stable top-K on scores s[j] = v[j+1], j in [0, N-1):
    // rank(j) = #{ i : s[i] > s[j]  or  (s[i] == s[j] and i < j) }
    // selected iff rank < KSEL.  Matches lax.top_k tie order.
    const float* vf = vbuf[cur];
    if (tid < N - 1) {
        const float sj = vf[tid + 1];
        int cnt = 0;
        #pragma unroll 4
        for (int i = 0; i < N - 1; ++i) {
            const float si = vf[i + 1];
            cnt += (si > sj) || (si == sj && i < tid);
        }
        if (cnt < KSEL) {
            // Selected: write the (0,1) one-hot. Same value from every
            // writer -> benign race.
            float2* o = (float2*)(out + 2 * (b * N + tid));
            *o = make_float2(0.0f, 1.0f);
        }
    }
    // Mask slot N-1 (=196) is never set: the reference writes top-k indices
    // of the 196-long score vector directly into the 197-long mask.
}

// ---------------------------------------------------------------------------
extern "C" void kernel_launch(void* const* d_in, const int* in_sizes, int n_in,
                              void* d_out, int out_size) {
    const float* rgb = (const float*)d_in[0];
    const float* tir = (const float*)d_in[1];
    float* out = (float*)d_out;

    (void)in_sizes; (void)n_in; (void)out_size;

    const int flags = BATCH * N;

    init_out_kernel<<<(flags + 255) / 256, 256>>>(out);
    chain_select_kernel<<<2 * BATCH * HEADS, 224>>>(rgb, tir, out);
}

// round 13
// speedup vs baseline: 2.2707x; 2.2707x over previous
#include <cuda_runtime.h>

// Problem constants
#define LAYERS 12
#define BATCH  16
#define HEADS  12
#define N      197
#define KSEL   98            // int(197 * 0.5)

#define HALF0  99            // rows [0, 99) -> half 0
#define TPH    224           // threads per half (7 warps)
#define TPB    448           // threads per block (14 warps)

// ---------------------------------------------------------------------------
// Kernel 0: paint output with the "unselected" one-hot (1, 0).
// out shape: [BATCH, N, 2] float32.
// ---------------------------------------------------------------------------
__global__ void init_out_kernel(float* __restrict__ out) {
    int t = blockIdx.x * blockDim.x + threadIdx.x;   // over BATCH*N
    if (t < BATCH * N) {
        out[2 * t + 0] = 1.0f;
        out[2 * t + 1] = 0.0f;
    }
}

// ---------------------------------------------------------------------------
// Kernel 1: one CTA per (modality, b, h), 448 threads.
//   Dot products split across two thread-halves (rows [0,99) / [99,197)),
//   combined in shared per layer. 16-deep LDG batches for MLP.
//   v = row 0 of A[11];  for l = 10..0:  v <- v^T * A[l]
//   scores s[j] = v[j+1]; stable top-98 (lower index wins ties, matching
//   lax.top_k); selected tokens write (0,1). Cross-CTA same-value races
//   are benign.
// ---------------------------------------------------------------------------
__global__ __launch_bounds__(TPB, 3)
void chain_select_kernel(const float* __restrict__ rgb,
                         const float* __restrict__ tir,
                         float* __restrict__ out) {
    const int bid = blockIdx.x;                 // [0, 2*BATCH*HEADS)
    const int mod = bid / (BATCH * HEADS);
    const int bh  = bid % (BATCH * HEADS);
    const int b   = bh / HEADS;

    const float* base = (mod == 0) ? rgb : tir;
    const size_t mat  = (size_t)N * N;

    __shared__ float vbuf[2][N];    // ping-pong chain vector
    __shared__ float part[N];       // half-1 partial sums

    const int tid  = threadIdx.x;
    const int half = tid / TPH;     // 0 or 1
    const int j    = tid % TPH;     // column owned (active if j < N)
    const int ilo  = half ? HALF0 : 0;
    const int ihi  = half ? N     : HALF0;

    // Init: vbuf[0] = A[11][b][h][0][:]  (only row 0 of layer 11 is needed)
    {
        const float* a11 = base + ((size_t)11 * BATCH * HEADS + (size_t)bh) * mat;
        if (tid < N) vbuf[0][tid] = __ldcs(&a11[tid]);
    }
    __syncthreads();

    // Chain: v <- v^T * A[l], l = 10 down to 0.
    int cur = 0;
    for (int l = 10; l >= 0; --l) {
        const float* __restrict__ A =
            base + ((size_t)l * BATCH * HEADS + (size_t)bh) * mat;
        const float* __restrict__ v = vbuf[cur];

        float acc = 0.0f;
        if (j < N) {
            const float* col = A + j;       // stride-N walk down column j
            int i = ilo;
            // 16-deep batches: all LDGs issued before any FMA consumes.
            #pragma unroll 1
            for (; i + 16 <= ihi; i += 16) {
                float a0  = __ldcs(&col[(size_t)(i +  0) * N]);
                float a1  = __ldcs(&col[(size_t)(i +  1) * N]);
                float a2  = __ldcs(&col[(size_t)(i +  2) * N]);
                float a3  = __ldcs(&col[(size_t)(i +  3) * N]);
                float a4  = __ldcs(&col[(size_t)(i +  4) * N]);
                float a5  = __ldcs(&col[(size_t)(i +  5) * N]);
                float a6  = __ldcs(&col[(size_t)(i +  6) * N]);
                float a7  = __ldcs(&col[(size_t)(i +  7) * N]);
                float a8  = __ldcs(&col[(size_t)(i +  8) * N]);
                float a9  = __ldcs(&col[(size_t)(i +  9) * N]);
                float a10 = __ldcs(&col[(size_t)(i + 10) * N]);
                float a11 = __ldcs(&col[(size_t)(i + 11) * N]);
                float a12 = __ldcs(&col[(size_t)(i + 12) * N]);
                float a13 = __ldcs(&col[(size_t)(i + 13) * N]);
                float a14 = __ldcs(&col[(size_t)(i + 14) * N]);
                float a15 = __ldcs(&col[(size_t)(i + 15) * N]);
                acc += v[i +  0] * a0;  acc += v[i +  1] * a1;
                acc += v[i +  2] * a2;  acc += v[i +  3] * a3;
                acc += v[i +  4] * a4;  acc += v[i +  5] * a5;
                acc += v[i +  6] * a6;  acc += v[i +  7] * a7;
                acc += v[i +  8] * a8;  acc += v[i +  9] * a9;
                acc += v[i + 10] * a10; acc += v[i + 11] * a11;
                acc += v[i + 12] * a12; acc += v[i + 13] * a13;
                acc += v[i + 14] * a14; acc += v[i + 15] * a15;
            }
            for (; i < ihi; ++i) {
                acc += v[i] * __ldcs(&col[(size_t)i * N]);
            }
        }

        // Combine halves: half 1 publishes, half 0 sums and writes new v.
        if (half == 1 && j < N) part[j] = acc;
        __syncthreads();
        if (half == 0 && j < N) vbuf[1 - cur][j] = acc + part[j];
        __syncthreads();
        cur = 1 - cur;
    }

    // Stable top-K on scores s[t] = v[t+1], t in [0, N-1):
    // rank(t) = #{ i : s[i] > s[t] or (s[i] == s[t] and i < t) }; select
    // iff rank < KSEL. Matches lax.top_k tie order.
    const float* vf = vbuf[cur];
    if (half == 0 && j < N - 1) {
        const float sj = vf[j + 1];
        int cnt = 0;
        #pragma unroll 4
        for (int i = 0; i < N - 1; ++i) {
            const float si = vf[i + 1];
            cnt += (si > sj) || (si == sj && i < j);
        }
        if (cnt < KSEL) {
            // Selected: (0,1) one-hot; identical value from every writer.
            float2* o = (float2*)(out + 2 * (b * N + j));
            *o = make_float2(0.0f, 1.0f);
        }
    }
    // Mask slot N-1 (=196) is never set: the reference writes top-k indices
    // of the 196-long score vector directly into the 197-long mask.
}

// ---------------------------------------------------------------------------
extern "C" void kernel_launch(void* const* d_in, const int* in_sizes, int n_in,
                              void* d_out, int out_size) {
    const float* rgb = (const float*)d_in[0];
    const float* tir = (const float*)d_in[1];
    float* out = (float*)d_out;

    (void)in_sizes; (void)n_in; (void)out_size;

    const int flags = BATCH * N;

    init_out_kernel<<<(flags + 255) / 256, 256>>>(out);
    chain_select_kernel<<<2 * BATCH * HEADS, TPB>>>(rgb, tir, out);
}